// round 1
// baseline (speedup 1.0000x reference)
#include <cuda_runtime.h>

typedef unsigned long long u64;

#define NH   10
#define NL   10
#define PPT  4
#define TPB  128

// ---- constant-memory weight layout (float offsets; all pair offsets even => 8B aligned) ----
#define OFF_W0   0      // [3][10]
#define OFF_B0   30     // [10]
#define OFF_W1   40     // [10][10]
#define OFF_B1   140    // [10]
#define OFF_WR1  150    // [10][10][10]
#define OFF_BR1  1150   // [10][10]
#define OFF_WR2  1250   // [10][10][10]
#define OFF_BR2  2250   // [10][10]
#define OFF_WR3  2350   // [10][10][10]
#define OFF_BR3  3350   // [10][10]
#define OFF_W8   3450   // [10][10]
#define OFF_B8   3550   // [10]
#define OFF_W9   3560   // [10][1]
#define OFF_B9   3570   // [1]
#define CW_TOTAL 3572

__constant__ __align__(16) float cw[CW_TOTAL];

// ---- packed f32x2 helpers (Blackwell FFMA2 path) ----
__device__ __forceinline__ u64 pk2(float lo, float hi) {
    u64 r; asm("mov.b64 %0, {%1, %2};" : "=l"(r) : "f"(lo), "f"(hi)); return r;
}
__device__ __forceinline__ void up2(u64 v, float& lo, float& hi) {
    asm("mov.b64 {%0, %1}, %2;" : "=f"(lo), "=f"(hi) : "l"(v));
}
__device__ __forceinline__ u64 fma2(u64 a, u64 b, u64 c) {
    u64 d; asm("fma.rn.f32x2 %0, %1, %2, %3;" : "=l"(d) : "l"(a), "l"(b), "l"(c)); return d;
}
__device__ __forceinline__ u64 add2(u64 a, u64 b) {
    u64 d; asm("add.rn.f32x2 %0, %1, %2;" : "=l"(d) : "l"(a), "l"(b)); return d;
}
// load a weight PAIR (two adjacent fan-out neurons) as one 8B constant load
__device__ __forceinline__ u64 ldc2(const float* p) {
    return *reinterpret_cast<const u64*>(p);
}

// out_j = relu( sum_k in_k * W[k][j] + B[j] ), j packed in pairs, PPT points at once
template<int K>
__device__ __forceinline__ void dense_relu(const float* W, const float* B,
                                           float hin[][K], float hout[][NH])
{
    u64 acc[PPT][NH/2];
#pragma unroll
    for (int j = 0; j < NH/2; j++) {
        u64 bp = ldc2(B + 2*j);
#pragma unroll
        for (int p = 0; p < PPT; p++) acc[p][j] = bp;
    }
#pragma unroll
    for (int k = 0; k < K; k++) {
        u64 hk[PPT];
#pragma unroll
        for (int p = 0; p < PPT; p++) hk[p] = pk2(hin[p][k], hin[p][k]);
#pragma unroll
        for (int j = 0; j < NH/2; j++) {
            u64 w = ldc2(W + k*NH + 2*j);
#pragma unroll
            for (int p = 0; p < PPT; p++) acc[p][j] = fma2(hk[p], w, acc[p][j]);
        }
    }
#pragma unroll
    for (int p = 0; p < PPT; p++)
#pragma unroll
        for (int j = 0; j < NH/2; j++) {
            float lo, hi; up2(acc[p][j], lo, hi);
            hout[p][2*j]   = fmaxf(lo, 0.0f);
            hout[p][2*j+1] = fmaxf(hi, 0.0f);
        }
}

// out = relu( h1 @ W3 + B3 + h0 @ W2 + B2 )
__device__ __forceinline__ void dense_res_relu(const float* W3, const float* B3,
                                               const float* W2, const float* B2,
                                               float h1[][NH], float h0[][NH],
                                               float hout[][NH])
{
    u64 acc[PPT][NH/2];
#pragma unroll
    for (int j = 0; j < NH/2; j++) {
        u64 bp = add2(ldc2(B3 + 2*j), ldc2(B2 + 2*j));
#pragma unroll
        for (int p = 0; p < PPT; p++) acc[p][j] = bp;
    }
#pragma unroll
    for (int k = 0; k < NH; k++) {
        u64 hk[PPT];
#pragma unroll
        for (int p = 0; p < PPT; p++) hk[p] = pk2(h1[p][k], h1[p][k]);
#pragma unroll
        for (int j = 0; j < NH/2; j++) {
            u64 w = ldc2(W3 + k*NH + 2*j);
#pragma unroll
            for (int p = 0; p < PPT; p++) acc[p][j] = fma2(hk[p], w, acc[p][j]);
        }
    }
#pragma unroll
    for (int k = 0; k < NH; k++) {
        u64 hk[PPT];
#pragma unroll
        for (int p = 0; p < PPT; p++) hk[p] = pk2(h0[p][k], h0[p][k]);
#pragma unroll
        for (int j = 0; j < NH/2; j++) {
            u64 w = ldc2(W2 + k*NH + 2*j);
#pragma unroll
            for (int p = 0; p < PPT; p++) acc[p][j] = fma2(hk[p], w, acc[p][j]);
        }
    }
#pragma unroll
    for (int p = 0; p < PPT; p++)
#pragma unroll
        for (int j = 0; j < NH/2; j++) {
            float lo, hi; up2(acc[p][j], lo, hi);
            hout[p][2*j]   = fmaxf(lo, 0.0f);
            hout[p][2*j+1] = fmaxf(hi, 0.0f);
        }
}

__global__ void __launch_bounds__(TPB)
resnet_kernel(const float4* __restrict__ x4, float4* __restrict__ out4, int nthreads)
{
    int t = blockIdx.x * TPB + threadIdx.x;
    if (t >= nthreads) return;

    // 4 points = 12 contiguous floats = 3 aligned float4 loads
    float4 a = x4[3*t + 0];
    float4 b = x4[3*t + 1];
    float4 c = x4[3*t + 2];
    float xin[PPT][3] = {
        {a.x, a.y, a.z},
        {a.w, b.x, b.y},
        {b.z, b.w, c.x},
        {c.y, c.z, c.w}
    };

    float h [PPT][NH];
    float h1[PPT][NH];

    dense_relu<3>(cw + OFF_W0, cw + OFF_B0, xin, h);
    dense_relu<NH>(cw + OFF_W1, cw + OFF_B1, h, h);

#pragma unroll 1   // keep SASS footprint ~25KB (under the I$ plateau)
    for (int l = 0; l < NL; l++) {
        const float* W1 = cw + OFF_WR1 + l*100;
        const float* B1 = cw + OFF_BR1 + l*10;
        const float* W2 = cw + OFF_WR2 + l*100;
        const float* B2 = cw + OFF_BR2 + l*10;
        const float* W3 = cw + OFF_WR3 + l*100;
        const float* B3 = cw + OFF_BR3 + l*10;
        dense_relu<NH>(W1, B1, h, h1);               // h1 = relu(h@W1+B1)
        dense_res_relu(W3, B3, W2, B2, h1, h, h);    // h  = relu(h1@W3+B3 + h@W2+B2)
    }

    dense_relu<NH>(cw + OFF_W8, cw + OFF_B8, h, h);

    // final [10]->[1] layer, scalar
    float o[PPT];
#pragma unroll
    for (int p = 0; p < PPT; p++) o[p] = cw[OFF_B9];
#pragma unroll
    for (int k = 0; k < NH; k++) {
        float wk = cw[OFF_W9 + k];
#pragma unroll
        for (int p = 0; p < PPT; p++) o[p] = fmaf(h[p][k], wk, o[p]);
    }
    out4[t] = make_float4(o[0], o[1], o[2], o[3]);
}

extern "C" void kernel_launch(void* const* d_in, const int* in_sizes, int n_in,
                              void* d_out, int out_size)
{
    // stage all weights into constant memory (D2D async copies: graph-capturable)
    static const int idx[14] = {1, 2, 3, 4, 5, 6, 7, 8, 9, 10, 11, 12, 13, 14};
    static const int off[14] = {OFF_W0, OFF_B0, OFF_W1, OFF_B1,
                                OFF_WR1, OFF_BR1, OFF_WR2, OFF_BR2, OFF_WR3, OFF_BR3,
                                OFF_W8, OFF_B8, OFF_W9, OFF_B9};
    static const int cnt[14] = {30, 10, 100, 10, 1000, 100, 1000, 100, 1000, 100, 100, 10, 10, 1};
    for (int i = 0; i < 14; i++) {
        cudaMemcpyToSymbolAsync(cw, d_in[idx[i]], (size_t)cnt[i] * sizeof(float),
                                (size_t)off[i] * sizeof(float),
                                cudaMemcpyDeviceToDevice, 0);
    }

    int npts     = in_sizes[0] / 3;          // x is [N,3]
    int nthreads = npts / PPT;               // N divisible by 4 (N = 4M)
    int nblocks  = (nthreads + TPB - 1) / TPB;
    resnet_kernel<<<nblocks, TPB>>>((const float4*)d_in[0], (float4*)d_out, nthreads);
}

// round 2
// speedup vs baseline: 1.1576x; 1.1576x over previous
#include <cuda_runtime.h>

#define NH   10
#define NL   10
#define TPB  128

// ---- constant-memory weight layout (float offsets; all even => pair-aligned) ----
#define OFF_W0   0      // [3][10]
#define OFF_B0   30     // [10]
#define OFF_W1   40     // [10][10]
#define OFF_B1   140    // [10]
#define OFF_WR1  150    // [10][10][10]
#define OFF_BR1  1150   // [10][10]
#define OFF_WR2  1250   // [10][10][10]
#define OFF_BR2  2250   // [10][10]
#define OFF_WR3  2350   // [10][10][10]
#define OFF_BR3  3350   // [10][10]
#define OFF_W8   3450   // [10][10]
#define OFF_B8   3550   // [10]
#define OFF_W9   3560   // [10][1]
#define OFF_B9   3570   // [1]
#define CW_TOTAL 3572
#define B23_OFF  3572   // precomputed (BR2+BR3) dup pairs, [10][10]
#define SW_TOTAL 3672

__constant__ __align__(16) float cw[CW_TOTAL];

__device__ __forceinline__ float2 f2(float x, float y) { return make_float2(x, y); }

// packed fp32x2 FMA (Blackwell FFMA2). Non-volatile: pure, let ptxas CSE/schedule.
// The mov.b64 pack/unpack coalesce into register-pair allocation (distinct halves).
__device__ __forceinline__ float2 ffma2(float2 a, float2 b, float2 c) {
    float2 d;
    asm("{\n\t"
        ".reg .b64 ra, rb, rc, rd;\n\t"
        "mov.b64 ra, {%2, %3};\n\t"
        "mov.b64 rb, {%4, %5};\n\t"
        "mov.b64 rc, {%6, %7};\n\t"
        "fma.rn.f32x2 rd, ra, rb, rc;\n\t"
        "mov.b64 {%0, %1}, rd;\n\t"
        "}"
        : "=f"(d.x), "=f"(d.y)
        : "f"(a.x), "f"(a.y), "f"(b.x), "f"(b.y), "f"(c.x), "f"(c.y));
    return d;
}

__device__ __forceinline__ float2 relu2(float2 v) {
    return f2(fmaxf(v.x, 0.0f), fmaxf(v.y, 0.0f));
}

// dense + relu: out[pp][j] = relu( sum_k h[pp][k] * W[k][j] + B[j] ), point-pair packed.
// W, B point into the SMEM dup table (each float stored as (w,w) float2).
template<int K>
__device__ __forceinline__ void dense(const float2* __restrict__ W,
                                      const float2* __restrict__ B,
                                      const float2 (&h)[2][K],
                                      float2 (&out)[2][NH])
{
    float2 acc[2][NH];
    // k = 0 folds the bias in as the addend (no separate init copies)
#pragma unroll
    for (int j2 = 0; j2 < NH/2; j2++) {
        float4 b = *reinterpret_cast<const float4*>(B + 2*j2);   // (b_j,b_j,b_j1,b_j1)
        float4 w = *reinterpret_cast<const float4*>(W + 2*j2);   // k=0 row
#pragma unroll
        for (int pp = 0; pp < 2; pp++) {
            acc[pp][2*j2+0] = ffma2(h[pp][0], f2(w.x, w.y), f2(b.x, b.y));
            acc[pp][2*j2+1] = ffma2(h[pp][0], f2(w.z, w.w), f2(b.z, b.w));
        }
    }
#pragma unroll
    for (int k = 1; k < K; k++) {
#pragma unroll
        for (int j2 = 0; j2 < NH/2; j2++) {
            float4 w = *reinterpret_cast<const float4*>(W + k*NH + 2*j2);
#pragma unroll
            for (int pp = 0; pp < 2; pp++) {
                acc[pp][2*j2+0] = ffma2(h[pp][k], f2(w.x, w.y), acc[pp][2*j2+0]);
                acc[pp][2*j2+1] = ffma2(h[pp][k], f2(w.z, w.w), acc[pp][2*j2+1]);
            }
        }
    }
#pragma unroll
    for (int pp = 0; pp < 2; pp++)
#pragma unroll
        for (int j = 0; j < NH; j++)
            out[pp][j] = relu2(acc[pp][j]);
}

// residual: out = relu( h1 @ W3 + h0 @ W2 + (B3 + B2) )   (B23 pre-summed dup pairs)
__device__ __forceinline__ void dense_res(const float2* __restrict__ W3,
                                          const float2* __restrict__ W2,
                                          const float2* __restrict__ B23,
                                          const float2 (&h1)[2][NH],
                                          const float2 (&h0)[2][NH],
                                          float2 (&out)[2][NH])
{
    float2 acc[2][NH];
#pragma unroll
    for (int j2 = 0; j2 < NH/2; j2++) {
        float4 b = *reinterpret_cast<const float4*>(B23 + 2*j2);
        float4 w = *reinterpret_cast<const float4*>(W3 + 2*j2);  // k=0 of W3
#pragma unroll
        for (int pp = 0; pp < 2; pp++) {
            acc[pp][2*j2+0] = ffma2(h1[pp][0], f2(w.x, w.y), f2(b.x, b.y));
            acc[pp][2*j2+1] = ffma2(h1[pp][0], f2(w.z, w.w), f2(b.z, b.w));
        }
    }
#pragma unroll
    for (int k = 1; k < NH; k++) {
#pragma unroll
        for (int j2 = 0; j2 < NH/2; j2++) {
            float4 w = *reinterpret_cast<const float4*>(W3 + k*NH + 2*j2);
#pragma unroll
            for (int pp = 0; pp < 2; pp++) {
                acc[pp][2*j2+0] = ffma2(h1[pp][k], f2(w.x, w.y), acc[pp][2*j2+0]);
                acc[pp][2*j2+1] = ffma2(h1[pp][k], f2(w.z, w.w), acc[pp][2*j2+1]);
            }
        }
    }
#pragma unroll
    for (int k = 0; k < NH; k++) {
#pragma unroll
        for (int j2 = 0; j2 < NH/2; j2++) {
            float4 w = *reinterpret_cast<const float4*>(W2 + k*NH + 2*j2);
#pragma unroll
            for (int pp = 0; pp < 2; pp++) {
                acc[pp][2*j2+0] = ffma2(h0[pp][k], f2(w.x, w.y), acc[pp][2*j2+0]);
                acc[pp][2*j2+1] = ffma2(h0[pp][k], f2(w.z, w.w), acc[pp][2*j2+1]);
            }
        }
    }
#pragma unroll
    for (int pp = 0; pp < 2; pp++)
#pragma unroll
        for (int j = 0; j < NH; j++)
            out[pp][j] = relu2(acc[pp][j]);
}

__global__ void __launch_bounds__(TPB)
resnet_kernel(const float4* __restrict__ x4, float4* __restrict__ out4, int nthreads)
{
    // build duplicated weight table in SMEM: sw[i] = (cw[i], cw[i]), plus B2+B3 sums
    __shared__ __align__(16) float2 sw[SW_TOTAL];
    for (int i = threadIdx.x; i < CW_TOTAL; i += TPB) {
        float w = cw[i];
        sw[i] = f2(w, w);
    }
    for (int i = threadIdx.x; i < 100; i += TPB) {
        float s = cw[OFF_BR2 + i] + cw[OFF_BR3 + i];
        sw[B23_OFF + i] = f2(s, s);
    }
    __syncthreads();

    int t = blockIdx.x * TPB + threadIdx.x;
    if (t >= nthreads) return;

    // 4 points = 12 contiguous floats = 3 aligned float4 loads
    float4 a = x4[3*t + 0];
    float4 b = x4[3*t + 1];
    float4 c = x4[3*t + 2];
    // point-pair packed input: x[pp][k] = (pt_{2pp}[k], pt_{2pp+1}[k])
    float2 xin[2][3] = {
        { f2(a.x, a.w), f2(a.y, b.x), f2(a.z, b.y) },
        { f2(b.z, c.y), f2(b.w, c.z), f2(c.x, c.w) }
    };

    float2 h [2][NH];
    float2 h1[2][NH];

    dense<3>(sw + OFF_W0, sw + OFF_B0, xin, h);
    dense<NH>(sw + OFF_W1, sw + OFF_B1, h, h);

#pragma unroll 1   // keep SASS footprint bounded (I$)
    for (int l = 0; l < NL; l++) {
        const float2* W1  = sw + OFF_WR1 + l*100;
        const float2* B1  = sw + OFF_BR1 + l*10;
        const float2* W2  = sw + OFF_WR2 + l*100;
        const float2* W3  = sw + OFF_WR3 + l*100;
        const float2* B23 = sw + B23_OFF + l*10;
        dense<NH>(W1, B1, h, h1);            // h1 = relu(h@W1+B1)
        dense_res(W3, W2, B23, h1, h, h);    // h  = relu(h1@W3 + h@W2 + B2+B3)
    }

    dense<NH>(sw + OFF_W8, sw + OFF_B8, h, h);

    // final [10]->[1] layer, point-pair packed
    float2 oA = sw[OFF_B9];   // (b9, b9)
    float2 oB = oA;
#pragma unroll
    for (int k = 0; k < NH; k++) {
        float2 wk = sw[OFF_W9 + k];   // (w_k, w_k)
        oA = ffma2(h[0][k], wk, oA);
        oB = ffma2(h[1][k], wk, oB);
    }
    out4[t] = make_float4(oA.x, oA.y, oB.x, oB.y);
}

extern "C" void kernel_launch(void* const* d_in, const int* in_sizes, int n_in,
                              void* d_out, int out_size)
{
    // stage all weights into constant memory (D2D async copies: graph-capturable)
    static const int idx[14] = {1, 2, 3, 4, 5, 6, 7, 8, 9, 10, 11, 12, 13, 14};
    static const int off[14] = {OFF_W0, OFF_B0, OFF_W1, OFF_B1,
                                OFF_WR1, OFF_BR1, OFF_WR2, OFF_BR2, OFF_WR3, OFF_BR3,
                                OFF_W8, OFF_B8, OFF_W9, OFF_B9};
    static const int cnt[14] = {30, 10, 100, 10, 1000, 100, 1000, 100, 1000, 100, 100, 10, 10, 1};
    for (int i = 0; i < 14; i++) {
        cudaMemcpyToSymbolAsync(cw, d_in[idx[i]], (size_t)cnt[i] * sizeof(float),
                                (size_t)off[i] * sizeof(float),
                                cudaMemcpyDeviceToDevice, 0);
    }

    int npts     = in_sizes[0] / 3;          // x is [N,3]
    int nthreads = npts / 4;                 // 4 points per thread (N = 4M)
    int nblocks  = (nthreads + TPB - 1) / TPB;
    resnet_kernel<<<nblocks, TPB>>>((const float4*)d_in[0], (float4*)d_out, nthreads);
}